// round 4
// baseline (speedup 1.0000x reference)
#include <cuda_runtime.h>
#include <math.h>

// ---------------------------------------------------------------------------
// HeatEquation1D: out = pad( u_inner @ (M^T)^100 )
// P = M^100 computed analytically in the discrete-sine eigenbasis (fp64),
// embedded zero-padded in g_P[64][64] (interior at [1..62][1..62], symmetric).
// Then one GEMM: Out[524288 x 64] = U * g_P.
// ---------------------------------------------------------------------------

#define PI_D 3.14159265358979323846

__device__ float g_P[64 * 64];

__global__ void build_P_kernel() {
    __shared__ float S[126];   // S[t] = sin(t*pi/63)
    __shared__ float w[62];    // w[m-1] = mu_m * (2/63)

    const int j = threadIdx.x;   // 0..63
    const int i = blockIdx.x;    // 0..63

    for (int t = j; t < 126; t += 64) {
        S[t] = (float)sin((double)t * (PI_D / 63.0));
    }
    if (j < 62) {
        const int m = j + 1;
        double s   = sin((double)m * (PI_D / 126.0));
        double lam = -4.0 * s * s;
        double dx  = 1.0 / 63.0;
        double alpha = 0.01 * 0.001 / (dx * dx);   // nu*dt/dx^2
        double g = (1.0 + 0.5 * alpha * lam) / (1.0 - 0.5 * alpha * lam);
        double g2 = g * g, g4 = g2 * g2, g8 = g4 * g4;
        double g16 = g8 * g8, g32 = g16 * g16, g64 = g32 * g32;
        double mu = g64 * g32 * g4;                 // g^100
        w[j] = (float)(mu * (2.0 / 63.0));
    }
    __syncthreads();

    float val = 0.0f;
    if (i >= 1 && i <= 62 && j >= 1 && j <= 62) {
        float acc = 0.0f;
        #pragma unroll 2
        for (int m = 1; m <= 62; m++) {
            int t1 = (m * i) % 126;
            int t2 = (m * j) % 126;
            acc += S[t1] * S[t2] * w[m - 1];
        }
        val = acc;
    }
    g_P[i * 64 + j] = val;
}

// ---------------------------------------------------------------------------
// GEMM: Out = U[524288x64] * g_P[64x64]
//
// K-packed f32x2 scheme: accumulator holds (even-k, odd-k) partial sums.
//   A operand  {U[r][2t], U[r][2t+1]}   : natural LDS.64 (k contiguous)
//   B operand  {P[2t][c], P[2t+1][c]}   : P symmetric -> stage rows of g_P
//                                         (Bs[c][k] = P[c][k] = P[k][c]),
//                                         k contiguous -> natural LDS.64
// g_P rows 0 and 63 are zero, so looping ALL 32 k-pairs (k=0..63) gives the
// correct interior-only contraction with no edge cases, and output columns
// 0 / 63 come out as exact zeros.
//
// Block: 128 threads, tile 64(M) x 64(N). Thread: 4 rows x 8 cols, columns
// strided (c = tx + 8j) so the 8 B LDS.64 addresses per pair land on 8
// distinct even banks (stride 66 => bank = 2c + 2t). A loads (stride 66)
// land on banks {2i+2t + 0,8,16,24} across ty. Fully conflict-free.
// Smem: 2 x 64*66*4 = 33792 B -> 4 blocks/SM (16 warps).
// Per k-pair per thread: 4 A-LDS.64 + 8 B-LDS.64 + 32 FFMA2, no splat MOVs.
// ---------------------------------------------------------------------------

#define MT 64

__global__ __launch_bounds__(128, 4)
void gemm_kernel(const float* __restrict__ U, float* __restrict__ Out) {
    __shared__ float As[64 * 66];
    __shared__ float Bs[64 * 66];

    const int tid = threadIdx.x;
    const int tx  = tid & 7;    // 0..7  -> cols c = tx + 8j
    const int ty  = tid >> 3;   // 0..15 -> rows r = ty*4 + i

    const long long rowBase = (long long)blockIdx.x * MT;
    const float4* U4 = (const float4*)(U + rowBase * 64);

    // Stage A: 64 rows x 16 float4, 8 float4 per thread, coalesced LDG.128.
    // STS as 2x float2 (stride 66 keeps rows 8B-aligned but not 16B).
    #pragma unroll
    for (int it = 0; it < 8; it++) {
        int idx = tid + it * 128;       // 0..1023 = r*16 + c4
        int r   = idx >> 4;
        int c4  = idx & 15;
        float4 v = U4[idx];
        float2* dst = (float2*)(As + r * 66 + c4 * 4);
        dst[0] = make_float2(v.x, v.y);
        dst[1] = make_float2(v.z, v.w);
    }

    // Stage B (P symmetric): Bs[c*66 + k] = g_P[c*64 + k], 32 scalars/thread.
    {
        const int c  = tid >> 1;
        const int k0 = (tid & 1) * 32;
        const float* src = g_P + c * 64 + k0;
        float* dst = Bs + c * 66 + k0;
        #pragma unroll
        for (int k = 0; k < 32; k++) {
            dst[k] = src[k];
        }
    }
    __syncthreads();

    unsigned long long acc[4][8];
    #pragma unroll
    for (int i = 0; i < 4; i++)
        #pragma unroll
        for (int j = 0; j < 8; j++)
            acc[i][j] = 0ULL;   // packed {0.0f, 0.0f}

    const float* arow = As + (ty * 4) * 66;
    const float* brow = Bs + tx * 66;

    #pragma unroll 4
    for (int t = 0; t < 32; t++) {
        unsigned long long a[4], b[8];
        #pragma unroll
        for (int i = 0; i < 4; i++)
            a[i] = *(const unsigned long long*)(arow + i * 66 + 2 * t);
        #pragma unroll
        for (int j = 0; j < 8; j++)
            b[j] = *(const unsigned long long*)(brow + j * 8 * 66 + 2 * t);

        #pragma unroll
        for (int i = 0; i < 4; i++)
            #pragma unroll
            for (int j = 0; j < 8; j++)
                asm("fma.rn.f32x2 %0, %1, %2, %0;"
                    : "+l"(acc[i][j]) : "l"(a[i]), "l"(b[j]));
    }

    // Epilogue: horizontal add of the two k-halves, scalar STG.
    // For each (r, j) the warp's 4 ty-groups x 8 tx lanes cover 4 full 32B
    // sectors -> fully-utilized coalesced stores.
    #pragma unroll
    for (int i = 0; i < 4; i++) {
        float* orow = Out + (rowBase + ty * 4 + i) * 64;
        #pragma unroll
        for (int j = 0; j < 8; j++) {
            unsigned int lo, hi;
            asm("mov.b64 {%0, %1}, %2;" : "=r"(lo), "=r"(hi) : "l"(acc[i][j]));
            orow[tx + 8 * j] = __uint_as_float(lo) + __uint_as_float(hi);
        }
    }
}

extern "C" void kernel_launch(void* const* d_in, const int* in_sizes, int n_in,
                              void* d_out, int out_size) {
    (void)in_sizes; (void)n_in; (void)out_size;
    const float* U = (const float*)d_in[0];   // u0 [524288 x 64] fp32
    float* Out = (float*)d_out;               // [524288 x 64] fp32

    build_P_kernel<<<64, 64>>>();
    gemm_kernel<<<524288 / MT, 128>>>(U, Out);
}